// round 4
// baseline (speedup 1.0000x reference)
#include <cuda_runtime.h>

// QLSTM: B=1024, T=512, F=32, H=128, NQ=4, NL=1.
// Closed-form VQC:  e = [z1z2z3, z0z1, z0z1z2, z0z1z2z3], z_q = cos(y_q + w_q).
// R4: TWO batch elements per warp (b, b+512) -> two independent dependency
//     chains interleaved via ILP inside each warp. 512 warps, 128 CTAs x 128thr.
//     Weights are shared between the two chains (lane role identical).

#define TQ 512
#define BB 1024
#define HH 128
#define FF 32

typedef unsigned long long u64;

__device__ __forceinline__ float frcp(float x) {
    float r; asm("rcp.approx.f32 %0, %1;" : "=f"(r) : "f"(x)); return r;
}
__device__ __forceinline__ float fex2(float x) {
    float r; asm("ex2.approx.f32 %0, %1;" : "=f"(r) : "f"(x)); return r;
}

// ---- f32x2 packed ops ----
__device__ __forceinline__ u64 pk(float a, float b) {
    u64 r; asm("mov.b64 %0, {%1, %2};" : "=l"(r) : "f"(a), "f"(b)); return r;
}
__device__ __forceinline__ u64 dup(float a) { return pk(a, a); }
__device__ __forceinline__ void upk(float& a, float& b, u64 v) {
    asm("mov.b64 {%0, %1}, %2;" : "=f"(a), "=f"(b) : "l"(v));
}
__device__ __forceinline__ u64 fma2(u64 a, u64 b, u64 c) {
    u64 d; asm("fma.rn.f32x2 %0, %1, %2, %3;" : "=l"(d) : "l"(a), "l"(b), "l"(c)); return d;
}
__device__ __forceinline__ u64 mul2(u64 a, u64 b) {
    u64 d; asm("mul.rn.f32x2 %0, %1, %2;" : "=l"(d) : "l"(a), "l"(b)); return d;
}

__global__ void __launch_bounds__(128, 1) qlstm_kernel(
    const float* __restrict__ x,      // [B,T,F]
    const float* __restrict__ W_in,   // [4,160]
    const float* __restrict__ b_in,   // [4]
    const float* __restrict__ W_out,  // [128,4]
    const float* __restrict__ b_out,  // [128]
    const float* __restrict__ w_f,    // [1,4]
    const float* __restrict__ w_i,
    const float* __restrict__ w_u,
    const float* __restrict__ w_o,
    float* __restrict__ out)          // [B*T*H] ++ [B*H] ++ [B*H]
{
    const int lane = threadIdx.x & 31;
    const int warp = threadIdx.x >> 5;
    const int b0 = blockIdx.x * 4 + warp;   // grid=128, 4 warps/CTA -> 0..511
    // batches handled: b0 and b0+512

    const int q = lane & 3;            // this lane's qubit duty
    const int g = (lane >> 2) & 3;     // this lane's gate duty (lanes 16+ duplicate)

    const float PI = 3.14159265358979f;

    // ---- shared per-lane constants ----
    float wh[4][4];                    // wh[m][qq] = W_in[qq][4*lane+m]
    #pragma unroll
    for (int m = 0; m < 4; m++)
        #pragma unroll
        for (int qq = 0; qq < 4; qq++)
            wh[m][qq] = W_in[qq * 160 + 4 * lane + m];
    float wx[4];                       // W_in[qq][128+lane]
    #pragma unroll
    for (int qq = 0; qq < 4; qq++)
        wx[qq] = W_in[qq * 160 + 128 + lane];
    const float bin = b_in[q];
    const float* wsel = (g == 0) ? w_f : (g == 1) ? w_i : (g == 2) ? w_u : w_o;
    const float wgp = wsel[q] + PI;

    u64 wo01[4], wo23[4];
    {
        float4 w0 = *(const float4*)&W_out[(4 * lane + 0) * 4];
        float4 w1 = *(const float4*)&W_out[(4 * lane + 1) * 4];
        float4 w2 = *(const float4*)&W_out[(4 * lane + 2) * 4];
        float4 w3 = *(const float4*)&W_out[(4 * lane + 3) * 4];
        wo01[0] = pk(w0.x, w1.x); wo01[1] = pk(w0.y, w1.y);
        wo01[2] = pk(w0.z, w1.z); wo01[3] = pk(w0.w, w1.w);
        wo23[0] = pk(w2.x, w3.x); wo23[1] = pk(w2.y, w3.y);
        wo23[2] = pk(w2.z, w3.z); wo23[3] = pk(w2.w, w3.w);
    }
    const u64 bo01 = pk(b_out[4 * lane + 0], b_out[4 * lane + 1]);
    const u64 bo23 = pk(b_out[4 * lane + 2], b_out[4 * lane + 3]);

    // packed poly constants
    const u64 CS3 = dup(2.0833333e-3f), CS2 = dup(-2.0833333e-2f);
    const u64 CS1 = dup(0.25f),         CSH = dup(0.5f);
    const u64 CT4 = dup(2.1869489e-2f), CT3 = dup(-5.3968254e-2f);
    const u64 CT2 = dup(1.3333333e-1f), CT1 = dup(-3.3333333e-1f);
    const u64 C1  = dup(1.0f);

    auto sig2 = [&](u64 xx) -> u64 {         // |x| <= ~1
        u64 x2 = mul2(xx, xx);
        u64 p = fma2(x2, CS3, CS2);
        p = fma2(x2, p, CS1);
        return fma2(xx, p, CSH);
    };
    auto th2 = [&](u64 xx) -> u64 {          // |x| <= ~0.7
        u64 x2 = mul2(xx, xx);
        u64 p = fma2(x2, CT4, CT3);
        p = fma2(x2, p, CT2);
        p = fma2(x2, p, CT1);
        p = fma2(x2, p, C1);
        return mul2(xx, p);
    };

    // ---- per-chain state (j = 0,1) ----
    float h0[2] = {0.f, 0.f}, h1[2] = {0.f, 0.f},
          h2[2] = {0.f, 0.f}, h3[2] = {0.f, 0.f};
    u64 c01[2] = {dup(0.f), dup(0.f)}, c23[2] = {dup(0.f), dup(0.f)};

    const float* xb[2];
    float* outb[2];
    float xc[2];
    #pragma unroll
    for (int j = 0; j < 2; j++) {
        int b = b0 + j * 512;
        xb[j] = x + (size_t)b * TQ * FF + lane;
        outb[j] = out + (size_t)b * TQ * HH + 4 * lane;
        xc[j] = xb[j][0];
    }

    const unsigned FULL = 0xffffffffu;
    const bool bit0 = (lane & 1) != 0;
    const bool bit1 = (lane & 2) != 0;

    for (int t = 0; t < TQ; t++) {
        const size_t xoff = (size_t)min(t + 1, TQ - 1) * FF;
        float xn[2];
        xn[0] = xb[0][xoff];
        xn[1] = xb[1][xoff];

        // ---- y partials (both chains) ----
        float p0[2], p1[2], p2[2], p3[2];
        #pragma unroll
        for (int j = 0; j < 2; j++) {
            p0[j] = wx[0] * xc[j]; p1[j] = wx[1] * xc[j];
            p2[j] = wx[2] * xc[j]; p3[j] = wx[3] * xc[j];
            p0[j] = fmaf(wh[0][0], h0[j], p0[j]); p1[j] = fmaf(wh[0][1], h0[j], p1[j]);
            p2[j] = fmaf(wh[0][2], h0[j], p2[j]); p3[j] = fmaf(wh[0][3], h0[j], p3[j]);
            p0[j] = fmaf(wh[1][0], h1[j], p0[j]); p1[j] = fmaf(wh[1][1], h1[j], p1[j]);
            p2[j] = fmaf(wh[1][2], h1[j], p2[j]); p3[j] = fmaf(wh[1][3], h1[j], p3[j]);
            p0[j] = fmaf(wh[2][0], h2[j], p0[j]); p1[j] = fmaf(wh[2][1], h2[j], p1[j]);
            p2[j] = fmaf(wh[2][2], h2[j], p2[j]); p3[j] = fmaf(wh[2][3], h2[j], p3[j]);
            p0[j] = fmaf(wh[3][0], h3[j], p0[j]); p1[j] = fmaf(wh[3][1], h3[j], p1[j]);
            p2[j] = fmaf(wh[3][2], h3[j], p2[j]); p3[j] = fmaf(wh[3][3], h3[j], p3[j]);
        }

        // ---- q-distributed butterfly (both chains, interleaved) ----
        float R[2];
        #pragma unroll
        for (int j = 0; j < 2; j++) {
            float sA = bit0 ? p0[j] : p1[j];
            float A  = (bit0 ? p1[j] : p0[j]) + __shfl_xor_sync(FULL, sA, 1);
            float sB = bit0 ? p2[j] : p3[j];
            float Bv = (bit0 ? p3[j] : p2[j]) + __shfl_xor_sync(FULL, sB, 1);
            float sC = bit1 ? A : Bv;
            float Rj = (bit1 ? Bv : A) + __shfl_xor_sync(FULL, sC, 2);
            Rj += __shfl_xor_sync(FULL, Rj, 4);
            Rj += __shfl_xor_sync(FULL, Rj, 8);
            Rj += __shfl_xor_sync(FULL, Rj, 16);
            R[j] = Rj;
        }

        // ---- MUFU chain + z (both chains) ----
        float z[2];
        #pragma unroll
        for (int j = 0; j < 2; j++) {
            float ypre = R[j] + bin;
            float e2x = fex2(ypre * 2.8853900818f);
            float r   = frcp(1.0f + e2x);
            float a   = fmaf(-6.2831853072f, r, wgp);
            z[j] = __cosf(a);
        }

        // ---- broadcast z, expvals, packed epilogue (both chains) ----
        #pragma unroll
        for (int j = 0; j < 2; j++) {
            u64 E0[4], E1[4], E2[4], E3[4];
            #pragma unroll
            for (int gg = 0; gg < 4; gg++) {
                float z0 = __shfl_sync(FULL, z[j], 4 * gg + 0);
                float z1 = __shfl_sync(FULL, z[j], 4 * gg + 1);
                float z2 = __shfl_sync(FULL, z[j], 4 * gg + 2);
                float z3 = __shfl_sync(FULL, z[j], 4 * gg + 3);
                float z23 = z2 * z3;
                float e1 = z0 * z1;
                E0[gg] = dup(z1 * z23);
                E1[gg] = dup(e1);
                E2[gg] = dup(e1 * z2);
                E3[gg] = dup(e1 * z23);
            }

            #pragma unroll
            for (int pair = 0; pair < 2; pair++) {
                const u64* wo = pair ? wo23 : wo01;
                u64 bo = pair ? bo23 : bo01;
                u64 aF = bo, aI = bo, aG = bo, aO = bo;
                aF = fma2(E0[0], wo[0], aF); aF = fma2(E1[0], wo[1], aF);
                aF = fma2(E2[0], wo[2], aF); aF = fma2(E3[0], wo[3], aF);
                aI = fma2(E0[1], wo[0], aI); aI = fma2(E1[1], wo[1], aI);
                aI = fma2(E2[1], wo[2], aI); aI = fma2(E3[1], wo[3], aI);
                aG = fma2(E0[2], wo[0], aG); aG = fma2(E1[2], wo[1], aG);
                aG = fma2(E2[2], wo[2], aG); aG = fma2(E3[2], wo[3], aG);
                aO = fma2(E0[3], wo[0], aO); aO = fma2(E1[3], wo[1], aO);
                aO = fma2(E2[3], wo[2], aO); aO = fma2(E3[3], wo[3], aO);

                u64 fg = sig2(aF);
                u64 ig = sig2(aI);
                u64 gg2 = th2(aG);
                u64 og = sig2(aO);
                u64 cold = pair ? c23[j] : c01[j];
                u64 cn = fma2(fg, cold, mul2(ig, gg2));
                u64 hn = mul2(og, th2(cn));
                if (pair == 0) { c01[j] = cn; upk(h0[j], h1[j], hn); }
                else           { c23[j] = cn; upk(h2[j], h3[j], hn); }
            }

            *(float4*)(outb[j] + (size_t)t * HH) =
                make_float4(h0[j], h1[j], h2[j], h3[j]);
            xc[j] = xn[j];
        }
    }

    // tail outputs: h_t then c_t
    const size_t base = (size_t)BB * TQ * HH;
    #pragma unroll
    for (int j = 0; j < 2; j++) {
        int b = b0 + j * 512;
        float c0, c1, c2, c3;
        upk(c0, c1, c01[j]); upk(c2, c3, c23[j]);
        *(float4*)(out + base + (size_t)b * HH + 4 * lane) =
            make_float4(h0[j], h1[j], h2[j], h3[j]);
        *(float4*)(out + base + (size_t)BB * HH + (size_t)b * HH + 4 * lane) =
            make_float4(c0, c1, c2, c3);
    }
}

extern "C" void kernel_launch(void* const* d_in, const int* in_sizes, int n_in,
                              void* d_out, int out_size) {
    const float* x     = (const float*)d_in[0];
    const float* W_in  = (const float*)d_in[1];
    const float* b_in  = (const float*)d_in[2];
    const float* W_out = (const float*)d_in[3];
    const float* b_out = (const float*)d_in[4];
    const float* w_f   = (const float*)d_in[5];
    const float* w_i   = (const float*)d_in[6];
    const float* w_u   = (const float*)d_in[7];
    const float* w_o   = (const float*)d_in[8];
    float* out = (float*)d_out;

    qlstm_kernel<<<128, 128>>>(x, W_in, b_in, W_out, b_out, w_f, w_i, w_u, w_o, out);
}